// round 6
// baseline (speedup 1.0000x reference)
#include <cuda_runtime.h>

// Problem constants (fixed by dataset: B=2, N=512, E=128, H=8, D=16)
#define B_    2
#define N_    512
#define E_    128
#define H_    8
#define D_    16
#define ROWS_ (B_ * N_)   // 1024

// Scratch (device globals: allocation-free rule)
__device__ float g_q[ROWS_ * E_];      // q * 0.25 (1/sqrt(D))
__device__ float g_v[ROWS_ * E_];
__device__ float g_esort[ROWS_ * N_];  // per-row ascending-sorted e

// ---------------------------------------------------------------------------
// K1: merged qv-projection + per-row bitonic sort of e.
//   blockIdx.x <  128 : qv GEMM tile (st = bx & 3, rowtile = bx >> 2)
//   blockIdx.x >= 128 : sort row (bx - 128) of e into g_esort
// 256 threads; dynamic smem 50 KB (qv); sort uses first 2 KB.
// ---------------------------------------------------------------------------
#define K1_SMEM_BYTES (32 * 128 * 4 + 128 * 68 * 4)

__global__ __launch_bounds__(256) void k1_kernel(const float* __restrict__ x,
                                                 const float* __restrict__ w_qkv,
                                                 const float* __restrict__ e) {
    extern __shared__ float sm[];
    const int tid = threadIdx.x;

    if (blockIdx.x >= 128) {
        // ---------------- bitonic sort of one e-row (512 elems) -------------
        const int row = blockIdx.x - 128;
        float* a = sm;   // 512 floats
        ((float4*)a)[tid] = ((const float4*)(e + row * N_))[tid & 127];
        // threads 128..255 duplicate loads of threads 0..127? avoid: guard
        __syncthreads();
        if (tid < 128) { /* already loaded by all; ensure single-writer: */ }
        // NOTE: the load above raced (two writers same value) — rewrite safely:
        __syncthreads();
        if (tid < 128) ((float4*)a)[tid] = ((const float4*)(e + row * N_))[tid];
        __syncthreads();

        for (int k = 2; k <= 512; k <<= 1) {
            for (int j = k >> 1; j > 0; j >>= 1) {
                int p = tid;                                   // 256 pairs
                int i = (p & (j - 1)) | ((p & ~(j - 1)) << 1);
                int l = i | j;
                bool up = (i & k) == 0;
                float av = a[i], bv = a[l];
                if ((av > bv) == up) { a[i] = bv; a[l] = av; }
                __syncthreads();
            }
        }
        if (tid < 128)
            ((float4*)(g_esort + row * N_))[tid] = ((const float4*)a)[tid];
        return;
    }

    // ------------------------- qv GEMM tile ---------------------------------
    float (*x_s)[128] = (float(*)[128])sm;
    float (*w_s)[68]  = (float(*)[68])(sm + 32 * 128);

    const int row0 = (blockIdx.x >> 2) * 32;
    const int st   = blockIdx.x & 3;                        // 0,1 -> q ; 2,3 -> v
    const int wbase = (st < 2) ? st * 64 : 128 + st * 64;   // 0,64,256,320
    const float* w_rows = w_qkv + wbase * 128;

    {
        const float4* x4 = (const float4*)(x + row0 * 128);
        float4* xs4 = (float4*)x_s;
        #pragma unroll
        for (int i = 0; i < 4; i++) xs4[tid + i * 256] = x4[tid + i * 256];
    }
    #pragma unroll
    for (int i = 0; i < 32; i++) {
        int idx = tid + i * 256;          // 0..8191
        int j = idx & 127, c = idx >> 7;
        w_s[j][c] = w_rows[c * 128 + j];
    }
    __syncthreads();

    const int tx = tid & 15, ty = tid >> 4;   // 4 cols, rows {ty, ty+16}
    float acc0[4] = {0, 0, 0, 0}, acc1[4] = {0, 0, 0, 0};
    #pragma unroll 4
    for (int jb = 0; jb < 32; jb++) {
        float4 xa4 = *(const float4*)&x_s[ty][jb * 4];
        float4 xb4 = *(const float4*)&x_s[ty + 16][jb * 4];
        float xa[4] = {xa4.x, xa4.y, xa4.z, xa4.w};
        float xb[4] = {xb4.x, xb4.y, xb4.z, xb4.w};
        #pragma unroll
        for (int k = 0; k < 4; k++) {
            float4 wv = *(const float4*)&w_s[jb * 4 + k][tx * 4];
            acc0[0] = fmaf(xa[k], wv.x, acc0[0]);
            acc0[1] = fmaf(xa[k], wv.y, acc0[1]);
            acc0[2] = fmaf(xa[k], wv.z, acc0[2]);
            acc0[3] = fmaf(xa[k], wv.w, acc0[3]);
            acc1[0] = fmaf(xb[k], wv.x, acc1[0]);
            acc1[1] = fmaf(xb[k], wv.y, acc1[1]);
            acc1[2] = fmaf(xb[k], wv.z, acc1[2]);
            acc1[3] = fmaf(xb[k], wv.w, acc1[3]);
        }
    }
    const float scale = (st < 2) ? 0.25f : 1.0f;
    float* dst = (st < 2) ? g_q : g_v;
    const int cg = (st & 1) * 64 + tx * 4;
    float4 o0 = {acc0[0] * scale, acc0[1] * scale, acc0[2] * scale, acc0[3] * scale};
    float4 o1 = {acc1[0] * scale, acc1[1] * scale, acc1[2] * scale, acc1[3] * scale};
    *(float4*)&dst[(row0 + ty) * 128 + cg]      = o0;
    *(float4*)&dst[(row0 + ty + 16) * 128 + cg] = o1;
}

// ---------------------------------------------------------------------------
// K2: attention + projection exploiting em in [0,1) and sorted e rows.
//
// For each d: a(em) = em*w + b on [0,1). If b*(w+b) >= 0, lrelu(a) is a fixed
// linear branch over the whole range -> folds into per-head constants.
// Otherwise ("active", t = -b/w in (0,1)): common branch (em > t) folds too;
// only em < t (a contiguous PREFIX of the sorted row, almost always tiny)
// needs a correction of the form kappa*(em*w + b).
//   phase1: s(em) = C0 + C1*em (+ prefix corrections)
//   phase2: sum_m p*lrelu = aV*S1 + bV*Z + [kw*E(t) + kb*P(t)] per active d,
//           P/E = prefix sums of p, p*em over em < t.
// ---------------------------------------------------------------------------
__global__ __launch_bounds__(256, 4) void attn_proj_kernel(const float* __restrict__ w_ekv,
                                                           const float* __restrict__ b_ekv,
                                                           const float* __restrict__ w_prj,
                                                           const float* __restrict__ b_prj,
                                                           float* __restrict__ out) {
    __shared__ float e_s[N_];
    __shared__ float q_s[128], v_s[128];
    __shared__ float wk_s[128], bk_s[128], wv_s[128], bv_s[128];
    __shared__ float4 listK[8][16];
    __shared__ float4 listV[8][16];
    __shared__ float prow[8][512];
    __shared__ float corr[128];
    __shared__ float hat_s[128];

    const int row  = blockIdx.x;
    const int tid  = threadIdx.x;
    const int lane = tid & 31;
    const int h    = tid >> 5;       // warp == head

    if (tid < 128)
        ((float4*)e_s)[tid] = ((const float4*)(g_esort + row * N_))[tid];
    if (tid < 128) {
        q_s[tid]  = g_q[row * 128 + tid];
        v_s[tid]  = g_v[row * 128 + tid];
        wk_s[tid] = w_ekv[tid];
        bk_s[tid] = b_ekv[tid];
    } else {
        int t = tid - 128;
        wv_s[t] = w_ekv[128 + t];
        bv_s[t] = b_ekv[128 + t];
    }
    __syncthreads();

    // ======== classification: K ========
    float C0K, C1K, tmaxK; int LK;
    {
        float w = 0.f, b = 0.f, qd = 0.f;
        bool act = false;
        if (lane < 16) {
            w = wk_s[h * 16 + lane]; b = bk_s[h * 16 + lane]; qd = q_s[h * 16 + lane];
            act = (b * (w + b) < 0.f);
        }
        float cw, cb;
        if (act) { bool wp = (w > 0.f); cw = wp ? w : 0.01f * w; cb = wp ? b : 0.01f * b; }
        else     { bool ps = (fmaf(0.5f, w, b) >= 0.f); cw = ps ? w : 0.01f * w; cb = ps ? b : 0.01f * b; }
        float c1 = qd * cw, c0 = qd * cb;
        float tm = act ? (-b / w) : 0.f;
        float tmx = tm;
        #pragma unroll
        for (int k = 16; k >= 1; k >>= 1) {
            c1 += __shfl_xor_sync(0xffffffffu, c1, k);
            c0 += __shfl_xor_sync(0xffffffffu, c0, k);
            tmx = fmaxf(tmx, __shfl_xor_sync(0xffffffffu, tmx, k));
        }
        C1K = c1; C0K = c0; tmaxK = tmx;
        unsigned m = __ballot_sync(0xffffffffu, act);
        LK = __popc(m);
        if (act) {
            int rank = __popc(m & ((1u << lane) - 1));
            float kap = (w > 0.f ? -0.99f : 0.99f) * qd;
            listK[h][rank] = make_float4(tm, kap * w, kap * b, 0.f);
        }
    }
    // ======== classification: V (per-lane aV,bV kept for epilogue) ========
    float aV = 0.f, bV = 0.f, tmaxV; int LV;
    {
        float w = 0.f, b = 0.f;
        bool act = false;
        if (lane < 16) {
            w = wv_s[h * 16 + lane]; b = bv_s[h * 16 + lane];
            act = (b * (w + b) < 0.f);
        }
        if (act) { bool wp = (w > 0.f); aV = wp ? w : 0.01f * w; bV = wp ? b : 0.01f * b; }
        else     { bool ps = (fmaf(0.5f, w, b) >= 0.f); aV = ps ? w : 0.01f * w; bV = ps ? b : 0.01f * b; }
        float tm = act ? (-b / w) : 0.f;
        float tmx = tm;
        #pragma unroll
        for (int k = 16; k >= 1; k >>= 1)
            tmx = fmaxf(tmx, __shfl_xor_sync(0xffffffffu, tmx, k));
        tmaxV = tmx;
        unsigned m = __ballot_sync(0xffffffffu, act);
        LV = __popc(m);
        if (act) {
            int rank = __popc(m & ((1u << lane) - 1));
            float kap = (w > 0.f ? -0.99f : 0.99f);
            listV[h][rank] = make_float4(tm, kap * w, kap * b, __int_as_float(lane));
        }
        if (lane < 16) corr[h * 16 + lane] = 0.f;
    }
    __syncwarp();

    // rare prefix extents (slots; e_s sorted ascending, slot i = [32i, 32i+32))
    int nrareK, nrareV;
    {
        bool fK = (lane < 16) && (e_s[lane * 32] < tmaxK);
        bool fV = (lane < 16) && (e_s[lane * 32] < tmaxV);
        nrareK = __popc(__ballot_sync(0xffffffffu, fK));
        nrareV = __popc(__ballot_sync(0xffffffffu, fV));
    }

    // ======== phase 1: scores ========
    float s[16];
    #pragma unroll
    for (int i = 0; i < 16; i++) {
        float em = e_s[i * 32 + lane];
        float sc = fmaf(C1K, em, C0K);
        if (i < nrareK) {
            for (int jj = 0; jj < LK; jj++) {
                float4 ent = listK[h][jj];
                if (em < ent.x) sc += fmaf(em, ent.y, ent.z);
            }
        }
        s[i] = sc;
    }

    // ======== softmax (Z, S1) ========
    float mx = s[0];
    #pragma unroll
    for (int i = 1; i < 16; i++) mx = fmaxf(mx, s[i]);
    #pragma unroll
    for (int k = 16; k >= 1; k >>= 1) mx = fmaxf(mx, __shfl_xor_sync(0xffffffffu, mx, k));
    float Z = 0.f, S1 = 0.f;
    #pragma unroll
    for (int i = 0; i < 16; i++) {
        s[i] = __expf(s[i] - mx);
        Z += s[i];
        S1 = fmaf(s[i], e_s[i * 32 + lane], S1);
    }
    #pragma unroll
    for (int k = 16; k >= 1; k >>= 1) {
        Z  += __shfl_xor_sync(0xffffffffu, Z, k);
        S1 += __shfl_xor_sync(0xffffffffu, S1, k);
    }
    const float invZ = 1.f / Z;

    // stage rare-prefix probabilities for the d-loop
    #pragma unroll
    for (int i = 0; i < 16; i++)
        if (i < nrareV) prow[h][i * 32 + lane] = s[i];
    __syncwarp();

    // ======== phase 2: per-active-d prefix corrections ========
    for (int jj = 0; jj < LV; jj++) {
        float4 ent = listV[h][jj];
        float P = 0.f, Ee = 0.f;
        for (int i = 0; i < nrareV; i++) {
            float em = e_s[i * 32 + lane];
            float p  = prow[h][i * 32 + lane];
            if (em < ent.x) { P += p; Ee = fmaf(p, em, Ee); }
        }
        #pragma unroll
        for (int k = 16; k >= 1; k >>= 1) {
            P  += __shfl_xor_sync(0xffffffffu, P, k);
            Ee += __shfl_xor_sync(0xffffffffu, Ee, k);
        }
        if (lane == 0)
            corr[h * 16 + __float_as_int(ent.w)] = fmaf(ent.y, Ee, ent.z * P);
    }
    __syncwarp();

    // ======== epilogue: hat ========
    if (lane < 16) {
        float num = fmaf(aV, S1, bV * Z) + corr[h * 16 + lane];
        hat_s[h * 16 + lane] = v_s[h * 16 + lane] + num * invZ;
    }
    __syncthreads();

    // ======== fused projection: warp h -> cols [h*16, h*16+16) ========
    {
        float4 h4 = ((const float4*)hat_s)[lane];
        float pc[16];
        #pragma unroll
        for (int i = 0; i < 16; i++) {
            const int c = h * 16 + i;
            float4 wv = *(const float4*)&w_prj[c * 128 + lane * 4];
            pc[i] = fmaf(h4.x, wv.x, fmaf(h4.y, wv.y, fmaf(h4.z, wv.z, h4.w * wv.w)));
        }
        #pragma unroll
        for (int r = 0; r < 4; r++) {
            const int half = 8 >> r;
            const bool hi = (lane >> r) & 1;
            #pragma unroll
            for (int j = 0; j < 8; j++) {
                if (j < half) {
                    float send = hi ? pc[j] : pc[j + half];
                    float keep = hi ? pc[j + half] : pc[j];
                    float recv = __shfl_xor_sync(0xffffffffu, send, 1 << r);
                    pc[j] = keep + recv;
                }
            }
        }
        float cval = pc[0] + __shfl_xor_sync(0xffffffffu, pc[0], 16);
        if (lane < 16) {
            int i = ((lane & 1) << 3) | (((lane >> 1) & 1) << 2)
                  | (((lane >> 2) & 1) << 1) | ((lane >> 3) & 1);
            const int c = h * 16 + i;
            out[row * 128 + c] = cval + b_prj[c];
        }
    }
}

// ---------------------------------------------------------------------------
extern "C" void kernel_launch(void* const* d_in, const int* in_sizes, int n_in,
                              void* d_out, int out_size) {
    const float* x     = (const float*)d_in[0];
    const float* e     = (const float*)d_in[1];
    const float* w_qkv = (const float*)d_in[2];
    const float* w_ekv = (const float*)d_in[3];
    const float* b_ekv = (const float*)d_in[4];
    const float* w_prj = (const float*)d_in[5];
    const float* b_prj = (const float*)d_in[6];
    float* out = (float*)d_out;

    cudaFuncSetAttribute((const void*)k1_kernel,
                         cudaFuncAttributeMaxDynamicSharedMemorySize, K1_SMEM_BYTES);

    k1_kernel       <<<128 + ROWS_, 256, K1_SMEM_BYTES>>>(x, w_qkv, e);
    attn_proj_kernel<<<ROWS_,       256>>>(w_ekv, b_ekv, w_prj, b_prj, out);
}

// round 7
// speedup vs baseline: 1.2171x; 1.2171x over previous
#include <cuda_runtime.h>

// Problem constants (fixed by dataset: B=2, N=512, E=128, H=8, D=16)
#define B_    2
#define N_    512
#define E_    128
#define H_    8
#define D_    16
#define ROWS_ (B_ * N_)   // 1024

// Scratch (device globals: allocation-free rule)
__device__ float g_q[ROWS_ * E_];    // q * 0.25 (1/sqrt(D))
__device__ float g_v[ROWS_ * E_];

// ---------------- packed fp32x2 helpers (Blackwell FFMA2/FADD2) -------------
typedef unsigned long long u64;
#define ABS2_MASK 0x7fffffff7fffffffULL

__device__ __forceinline__ u64 pack2(float lo, float hi) {
    u64 r; asm("mov.b64 %0, {%1, %2};" : "=l"(r) : "f"(lo), "f"(hi)); return r;
}
__device__ __forceinline__ float2 unpk2(u64 v) {
    float2 f; asm("mov.b64 {%0, %1}, %2;" : "=f"(f.x), "=f"(f.y) : "l"(v)); return f;
}
__device__ __forceinline__ u64 ffma2(u64 a, u64 b, u64 c) {
    u64 d; asm("fma.rn.f32x2 %0, %1, %2, %3;" : "=l"(d) : "l"(a), "l"(b), "l"(c)); return d;
}
__device__ __forceinline__ u64 fadd2(u64 a, u64 b) {
    u64 d; asm("add.rn.f32x2 %0, %1, %2;" : "=l"(d) : "l"(a), "l"(b)); return d;
}

// ---------------------------------------------------------------------------
// qv GEMM: C[32r x 64c] = X[32 x 128] @ W[64 x 128]^T per CTA (measured 3.7us;
// identical to Round 5).
// ---------------------------------------------------------------------------
#define QV_SMEM_BYTES (32 * 128 * 4 + 128 * 68 * 4)

__global__ __launch_bounds__(128) void qv_kernel(const float* __restrict__ x,
                                                 const float* __restrict__ w_qkv) {
    extern __shared__ float sm[];
    float (*x_s)[128] = (float(*)[128])sm;
    float (*w_s)[68]  = (float(*)[68])(sm + 32 * 128);

    const int tid  = threadIdx.x;
    const int row0 = blockIdx.y * 32;
    const int st   = blockIdx.x;                           // 0,1 -> q ; 2,3 -> v
    const int wbase = (st < 2) ? st * 64 : 128 + st * 64;  // 0,64,256,320
    const float* w_rows = w_qkv + wbase * 128;

    {
        const float4* x4 = (const float4*)(x + row0 * 128);
        float4* xs4 = (float4*)x_s;
        #pragma unroll
        for (int i = 0; i < 8; i++) xs4[tid + i * 128] = x4[tid + i * 128];
    }
    #pragma unroll
    for (int i = 0; i < 64; i++) {
        int idx = tid + i * 128;
        int j = idx & 127, c = idx >> 7;
        w_s[j][c] = w_rows[c * 128 + j];
    }
    __syncthreads();

    const int tx = tid & 15;
    const int ty = tid >> 4;
    float acc[4][4];
    #pragma unroll
    for (int r = 0; r < 4; r++)
        #pragma unroll
        for (int c = 0; c < 4; c++) acc[r][c] = 0.f;

    #pragma unroll 4
    for (int jb = 0; jb < 32; jb++) {
        float4 xr[4], wv[4];
        #pragma unroll
        for (int r = 0; r < 4; r++) xr[r] = *(const float4*)&x_s[ty * 4 + r][jb * 4];
        #pragma unroll
        for (int k = 0; k < 4; k++) wv[k] = *(const float4*)&w_s[jb * 4 + k][tx * 4];
        #pragma unroll
        for (int k = 0; k < 4; k++) {
            float xk[4] = {xr[0].x, xr[1].x, xr[2].x, xr[3].x};
            if (k == 1) { xk[0] = xr[0].y; xk[1] = xr[1].y; xk[2] = xr[2].y; xk[3] = xr[3].y; }
            if (k == 2) { xk[0] = xr[0].z; xk[1] = xr[1].z; xk[2] = xr[2].z; xk[3] = xr[3].z; }
            if (k == 3) { xk[0] = xr[0].w; xk[1] = xr[1].w; xk[2] = xr[2].w; xk[3] = xr[3].w; }
            #pragma unroll
            for (int r = 0; r < 4; r++) {
                acc[r][0] = fmaf(xk[r], wv[k].x, acc[r][0]);
                acc[r][1] = fmaf(xk[r], wv[k].y, acc[r][1]);
                acc[r][2] = fmaf(xk[r], wv[k].z, acc[r][2]);
                acc[r][3] = fmaf(xk[r], wv[k].w, acc[r][3]);
            }
        }
    }

    const float scale = (st < 2) ? 0.25f : 1.0f;
    float* dst = (st < 2) ? g_q : g_v;
    const int cg = (st & 1) * 64 + tx * 4;
    #pragma unroll
    for (int r = 0; r < 4; r++) {
        float4 o = {acc[r][0] * scale, acc[r][1] * scale, acc[r][2] * scale, acc[r][3] * scale};
        *(float4*)&dst[(row0 + ty * 4 + r) * 128 + cg] = o;
    }
}

// ---------------------------------------------------------------------------
// Fused attention + projection (Round-5 engine + single-pass softmax).
// One CTA per (b,n), warp = head, 16 m per lane, packed f32x2 over d-pairs.
//
// Reparam:  lrelu(em*w + b) = 0.505(em*w + b) + 0.495|w|*|em + b/w|
//   s[m]   = c0 + c1*em + sum_d g_d |em + r_d|
//   p[m]   = exp(s[m] - B),  B = sum_d |q_d| max(|b_d|, |w_d+b_d|) >= max s
//   (the bound-shift cancels exactly in p/Z; no max pass needed)
//   hat_d  = v_d + [0.505(wv_d*S1 + bv_d*Z) + 0.495|wv_d| * sum_m p|em+rv_d|]/Z
// e staged as duplicated pairs (em,em) so LDS.64 feeds FFMA2 directly.
// ---------------------------------------------------------------------------
__global__ __launch_bounds__(256, 3) void attn_proj_kernel(const float* __restrict__ e,
                                                           const float* __restrict__ w_ekv,
                                                           const float* __restrict__ b_ekv,
                                                           const float* __restrict__ w_prj,
                                                           const float* __restrict__ b_prj,
                                                           float* __restrict__ out) {
    __shared__ u64   e2_s[N_];                 // (em, em) duplicated pairs
    __shared__ float q_s[128], v_s[128];
    __shared__ float wk_s[128], bk_s[128], wv_s[128], bv_s[128];
    __shared__ float hat_s[128];

    const int row  = blockIdx.x;     // b*N + n
    const int tid  = threadIdx.x;
    const int lane = tid & 31;
    const int h    = tid >> 5;       // warp == head

    {
        float e0 = e[row * N_ + tid];
        float e1 = e[row * N_ + 256 + tid];
        e2_s[tid]       = pack2(e0, e0);
        e2_s[tid + 256] = pack2(e1, e1);
    }
    if (tid < 128) {
        q_s[tid]  = g_q[row * 128 + tid];
        v_s[tid]  = g_v[row * 128 + tid];
        wk_s[tid] = w_ekv[tid];
        bk_s[tid] = b_ekv[tid];
    } else {
        int t = tid - 128;
        wv_s[t] = w_ekv[128 + t];
        bv_s[t] = b_ekv[128 + t];
    }
    __syncthreads();

    float s[16];
    float Z = 0.f, S1 = 0.f;

    // ======== phase 1: scores + inline exp/Z/S1 (single pass) ========
    {
        u64 r2[8], g2[8];
        float c0 = 0.f, c1 = 0.f, B = 0.f;
        #pragma unroll
        for (int dd = 0; dd < 8; dd++) {
            float2 w = ((const float2*)wk_s)[h * 8 + dd];
            float2 b = ((const float2*)bk_s)[h * 8 + dd];
            float2 q = ((const float2*)q_s)[h * 8 + dd];
            r2[dd] = pack2(__fdividef(b.x, w.x), __fdividef(b.y, w.y));
            g2[dd] = pack2(0.495f * q.x * fabsf(w.x), 0.495f * q.y * fabsf(w.y));
            c1 = fmaf(q.x, w.x, fmaf(q.y, w.y, c1));
            c0 = fmaf(q.x, b.x, fmaf(q.y, b.y, c0));
            B  = fmaf(fabsf(q.x), fmaxf(fabsf(b.x), fabsf(w.x + b.x)),
                 fmaf(fabsf(q.y), fmaxf(fabsf(b.y), fabsf(w.y + b.y)), B));
        }
        c1 *= 0.505f; c0 *= 0.505f;
        c0 -= B;   // fold the softmax bound into the affine constant

        #pragma unroll
        for (int i = 0; i < 16; i++) {
            const u64 em2 = e2_s[i * 32 + lane];
            const float em = unpk2(em2).x;
            u64 acc2 = 0ULL;
            #pragma unroll
            for (int dd = 0; dd < 8; dd++) {
                u64 u2 = fadd2(em2, r2[dd]);
                acc2 = ffma2(g2[dd], u2 & ABS2_MASK, acc2);
            }
            float2 f = unpk2(acc2);
            float p = __expf(fmaf(c1, em, c0) + f.x + f.y);
            s[i] = p;
            Z += p;
            S1 = fmaf(p, em, S1);
        }
    }
    #pragma unroll
    for (int k = 16; k >= 1; k >>= 1) {
        Z  += __shfl_xor_sync(0xffffffffu, Z, k);
        S1 += __shfl_xor_sync(0xffffffffu, S1, k);
    }
    const float invZ = 1.f / Z;

    // ======== phase 2: acc_d = sum_m p |em + bv_d/wv_d| ========
    float acc[16];
    {
        u64 rv2[8], acc2[8];
        #pragma unroll
        for (int dd = 0; dd < 8; dd++) {
            float2 w = ((const float2*)wv_s)[h * 8 + dd];
            float2 b = ((const float2*)bv_s)[h * 8 + dd];
            rv2[dd] = pack2(__fdividef(b.x, w.x), __fdividef(b.y, w.y));
            acc2[dd] = 0ULL;
        }
        #pragma unroll
        for (int i = 0; i < 16; i++) {
            const u64 em2 = e2_s[i * 32 + lane];
            const u64 p2  = pack2(s[i], s[i]);
            #pragma unroll
            for (int dd = 0; dd < 8; dd++) {
                u64 u2 = fadd2(em2, rv2[dd]);
                acc2[dd] = ffma2(p2, u2 & ABS2_MASK, acc2[dd]);
            }
        }
        #pragma unroll
        for (int dd = 0; dd < 8; dd++) {
            float2 fb = unpk2(acc2[dd]);
            acc[2 * dd]     = fb.x;
            acc[2 * dd + 1] = fb.y;
        }
    }

    // ---- butterfly transpose-reduce: lane L ends with d = bitrev4(L&15) ----
    #pragma unroll
    for (int r = 0; r < 4; r++) {
        const int half = 8 >> r;
        const bool hi = (lane >> r) & 1;
        #pragma unroll
        for (int j = 0; j < 8; j++) {
            if (j < half) {
                float send = hi ? acc[j] : acc[j + half];
                float keep = hi ? acc[j + half] : acc[j];
                float recv = __shfl_xor_sync(0xffffffffu, send, 1 << r);
                acc[j] = keep + recv;
            }
        }
    }
    float tot = acc[0] + __shfl_xor_sync(0xffffffffu, acc[0], 16);
    if (lane < 16) {
        int d = ((lane & 1) << 3) | (((lane >> 1) & 1) << 2)
              | (((lane >> 2) & 1) << 1) | ((lane >> 3) & 1);
        float wvd = wv_s[h * 16 + d], bvd = bv_s[h * 16 + d];
        float lin = 0.505f * fmaf(wvd, S1, bvd * Z);
        hat_s[h * 16 + d] = v_s[h * 16 + d]
                          + fmaf(0.495f * fabsf(wvd), tot, lin) * invZ;
    }
    __syncthreads();

    // ======== fused projection: warp h -> cols [h*16, h*16+16) ========
    {
        float4 h4 = ((const float4*)hat_s)[lane];   // hat[lane*4 .. +3]
        float pc[16];
        #pragma unroll
        for (int i = 0; i < 16; i++) {
            const int c = h * 16 + i;
            float4 wv = *(const float4*)&w_prj[c * 128 + lane * 4];
            pc[i] = fmaf(h4.x, wv.x, fmaf(h4.y, wv.y, fmaf(h4.z, wv.z, h4.w * wv.w)));
        }
        #pragma unroll
        for (int r = 0; r < 4; r++) {
            const int half = 8 >> r;
            const bool hi = (lane >> r) & 1;
            #pragma unroll
            for (int j = 0; j < 8; j++) {
                if (j < half) {
                    float send = hi ? pc[j] : pc[j + half];
                    float keep = hi ? pc[j + half] : pc[j];
                    float recv = __shfl_xor_sync(0xffffffffu, send, 1 << r);
                    pc[j] = keep + recv;
                }
            }
        }
        float cval = pc[0] + __shfl_xor_sync(0xffffffffu, pc[0], 16);
        if (lane < 16) {
            int i = ((lane & 1) << 3) | (((lane >> 1) & 1) << 2)
                  | (((lane >> 2) & 1) << 1) | ((lane >> 3) & 1);
            const int c = h * 16 + i;
            out[row * 128 + c] = cval + b_prj[c];
        }
    }
}

// ---------------------------------------------------------------------------
extern "C" void kernel_launch(void* const* d_in, const int* in_sizes, int n_in,
                              void* d_out, int out_size) {
    const float* x     = (const float*)d_in[0];
    const float* e     = (const float*)d_in[1];
    const float* w_qkv = (const float*)d_in[2];
    const float* w_ekv = (const float*)d_in[3];
    const float* b_ekv = (const float*)d_in[4];
    const float* w_prj = (const float*)d_in[5];
    const float* b_prj = (const float*)d_in[6];
    float* out = (float*)d_out;

    cudaFuncSetAttribute((const void*)qv_kernel,
                         cudaFuncAttributeMaxDynamicSharedMemorySize, QV_SMEM_BYTES);

    qv_kernel       <<<dim3(4, 32), 128, QV_SMEM_BYTES>>>(x, w_qkv);
    attn_proj_kernel<<<ROWS_,       256>>>(e, w_ekv, b_ekv, w_prj, b_prj, out);
}